// round 5
// baseline (speedup 1.0000x reference)
#include <cuda_runtime.h>
#include <cuda_fp16.h>
#include <stdint.h>

#define FDIM   1024
#define BATCH  256
#define NCLS   1000
#define CPAD   1024
#define KROW   65536        // F*DOF per W row
#define CB     16           // class blocks of 64
#define FS     8            // f slices of 128
#define FPC    128          // f per CTA
#define THREADS 512

// ---------------- static device scratch ----------------
__device__ uint32_t g_meta2[FDIM * BATCH];               // [f][b]: (t<<16)|lam0_f16
__device__ float    g_part[(size_t)FS * BATCH * CPAD];   // [fs][b][c]
__device__ float    g_rspart[FS * CPAD];                 // [fs][c]

// ---------------- Kernel 1: packed meta with smem transpose ----------------
__global__ void __launch_bounds__(1024) embed_k(const float* __restrict__ x,
                                                const float* __restrict__ mn,
                                                const float* __restrict__ mx) {
    __shared__ uint32_t sm[32][33];
    const int tx = threadIdx.x & 31;
    const int ty = threadIdx.x >> 5;
    const int f0 = blockIdx.x * 32;
    const int b0 = blockIdx.y * 32;

    const float mnv = mn[0], mxv = mx[0];
    const float s = (x[(size_t)(b0 + ty) * FDIM + f0 + tx] - mnv) / (mxv - mnv) * 63.0f;

    uint32_t m;
    if (s >= 0.0f && s <= 63.0f) {
        int t = (int)s;
        if (t > 62) t = 62;
        const float l0 = s - (float)t;     // -> vertex t+1 ; lam1 = 1 - l0 -> vertex t
        m = ((uint32_t)t << 16) | (uint32_t)__half_as_ushort(__float2half_rn(l0));
    } else {
        m = 63u << 16;                     // points at the always-zero tile row
    }
    sm[ty][tx] = m;
    __syncthreads();
    g_meta2[(size_t)(f0 + ty) * BATCH + b0 + tx] = sm[tx][ty];
}

// ---------------- Kernel 2: f16-pair smem gather ----------------
// CTA: 64 classes (cb) x 128 f (fs) x 256 b.
// tile[t][cls] = half2(w[t], w[t+1]) ; row 63 forced zero (invalid-x sink).
// gather: lane -> classes (2*lane, 2*lane+1); warp w -> b in [w*16, w*16+16).
__global__ void __launch_bounds__(THREADS, 1) gather_k(const float* __restrict__ W) {
    __shared__ uint32_t sm_tile[2][64 * 64];   // 2 x 16 KB
    __shared__ uint32_t sm_meta[2][256];       // 2 x 1 KB
    __shared__ float    sm_rs[16][64];         // 4 KB

    const int tid  = threadIdx.x;
    const int lane = tid & 31;
    const int w    = tid >> 5;          // 0..15 : dof colgroup (4w..4w+3)
    const int cb   = blockIdx.x;        // 0..15
    const int fs   = blockIdx.y;        // 0..7
    const int fbase = fs * FPC;

    // fill pointers: pass p -> class row p*32+lane (clamped; rows >=1000 never read back)
    const float* wp[2];
    #pragma unroll
    for (int p = 0; p < 2; p++) {
        int row = cb * 64 + p * 32 + lane;
        if (row > NCLS - 1) row = NCLS - 1;
        wp[p] = W + (size_t)row * KROW + (size_t)fbase * 64 + w * 4;
    }
    const uint32_t* mp = g_meta2 + (size_t)fbase * BATCH + tid;   // used when tid<256

    float    accf[2][16];
    uint32_t acch[2][16];
    #pragma unroll
    for (int k = 0; k < 2; k++)
        #pragma unroll
        for (int j = 0; j < 16; j++) { accf[k][j] = 0.f; acch[k][j] = 0u; }
    float rs[2] = {0.f, 0.f};

    // prologue prefetch (f0)
    float4 wv[2]; float w5[2] = {0.f, 0.f}; uint32_t mreg = 0;
    #pragma unroll
    for (int p = 0; p < 2; p++) {
        wv[p] = *(const float4*)(wp[p]);
        if (w < 15) w5[p] = wp[p][4];
    }
    if (tid < 256) mreg = mp[0];

    const __half one = __ushort_as_half((unsigned short)0x3C00);

    for (int fi = 0; fi < FPC; fi++) {
        const int buf = fi & 1;
        uint32_t* tb = sm_tile[buf];

        // ---- fill pair tile (+ inline rowsum) ----
        #pragma unroll
        for (int p = 0; p < 2; p++) {
            const float4 v = wv[p];
            rs[p] += (v.x + v.y) + (v.z + v.w);
            uint32_t pr[4]; __half2 h;
            h = __floats2half2_rn(v.x, v.y);   pr[0] = *(uint32_t*)&h;
            h = __floats2half2_rn(v.y, v.z);   pr[1] = *(uint32_t*)&h;
            h = __floats2half2_rn(v.z, v.w);   pr[2] = *(uint32_t*)&h;
            h = __floats2half2_rn(v.w, w5[p]); pr[3] = *(uint32_t*)&h;
            if (w == 15) pr[3] = 0u;           // t=63 row: always zero (invalid sink)
            const int cls = p * 32 + lane;
            #pragma unroll
            for (int i = 0; i < 4; i++)
                tb[(w * 4 + i) * 64 + cls] = pr[i];
        }
        if (tid < 256) sm_meta[buf][tid] = mreg;
        __syncthreads();

        // ---- prefetch next f into regs (hidden under gather) ----
        if (fi + 1 < FPC) {
            #pragma unroll
            for (int p = 0; p < 2; p++) {
                wv[p] = *(const float4*)(wp[p] + (size_t)(fi + 1) * 64);
                if (w < 15) w5[p] = wp[p][(size_t)(fi + 1) * 64 + 4];
            }
            if (tid < 256) mreg = mp[(size_t)(fi + 1) * BATCH];
        }

        // ---- gather: 16 b's, one LDS.64 per b (two classes/lane) ----
        const uint32_t* mb = sm_meta[buf];
        #pragma unroll
        for (int q = 0; q < 4; q++) {
            const uint4 mq = *(const uint4*)(mb + w * 16 + q * 4);
            const uint32_t ms[4] = {mq.x, mq.y, mq.z, mq.w};
            #pragma unroll
            for (int jj = 0; jj < 4; jj++) {
                const int j = q * 4 + jj;
                const uint32_t m = ms[jj];
                const uint32_t row = m >> 16;
                const __half l0 = __ushort_as_half((unsigned short)(m & 0xffffu));
                const __half2 lam2 = __halves2half2(__hsub(one, l0), l0);
                const uint2 pp = *(const uint2*)(tb + row * 64 + lane * 2);
                __half2 a0 = *(const __half2*)&acch[0][j];
                __half2 a1 = *(const __half2*)&acch[1][j];
                a0 = __hfma2(lam2, *(const __half2*)&pp.x, a0);
                a1 = __hfma2(lam2, *(const __half2*)&pp.y, a1);
                acch[0][j] = *(const uint32_t*)&a0;
                acch[1][j] = *(const uint32_t*)&a1;
            }
        }

        // ---- drain f16 accumulators to fp32 every 16 f ----
        if ((fi & 15) == 15) {
            #pragma unroll
            for (int k = 0; k < 2; k++)
                #pragma unroll
                for (int j = 0; j < 16; j++) {
                    const float2 f2 = __half22float2(*(const __half2*)&acch[k][j]);
                    accf[k][j] += f2.x + f2.y;
                    acch[k][j] = 0u;
                }
        }
    }

    // ---- rowsum reduce across the 16 colgroup warps ----
    #pragma unroll
    for (int p = 0; p < 2; p++) sm_rs[w][p * 32 + lane] = rs[p];
    __syncthreads();
    if (tid < 64) {
        float r = 0.f;
        #pragma unroll
        for (int ww = 0; ww < 16; ww++) r += sm_rs[ww][tid];
        g_rspart[fs * CPAD + cb * 64 + tid] = r;
    }

    // ---- store partials: coalesced float2 per lane ----
    const int b0 = w * 16;
    #pragma unroll
    for (int j = 0; j < 16; j++) {
        float2 val = make_float2(accf[0][j], accf[1][j]);
        *(float2*)(g_part + ((size_t)fs * BATCH + b0 + j) * CPAD + cb * 64 + lane * 2) = val;
    }
}

// ---------------- Kernel 3: reduce partials + rowsum term ----------------
__global__ void __launch_bounds__(256) epi_k(const float* __restrict__ mn,
                                             const float* __restrict__ mx,
                                             float* __restrict__ out) {
    const int b = blockIdx.x;            // 0..255
    const float mnv = mn[0], mxv = mx[0];
    const float sc = mxv - mnv;
    for (int c = threadIdx.x; c < NCLS; c += 256) {
        float s = 0.f, rsum = 0.f;
        #pragma unroll
        for (int fsl = 0; fsl < FS; fsl++) {
            s    += g_part[((size_t)fsl * BATCH + b) * CPAD + c];
            rsum += g_rspart[fsl * CPAD + c];
        }
        out[(size_t)b * NCLS + c] = sc * s + mnv * rsum;
    }
}

// ---------------- launch ----------------
extern "C" void kernel_launch(void* const* d_in, const int* in_sizes, int n_in,
                              void* d_out, int out_size) {
    const float* x  = (const float*)d_in[0];
    const float* mn = (const float*)d_in[1];
    const float* mx = (const float*)d_in[2];
    const float* W  = (const float*)d_in[3];
    float* out = (float*)d_out;

    embed_k<<<dim3(32, 8), 1024>>>(x, mn, mx);
    gather_k<<<dim3(CB, FS), THREADS>>>(W);
    epi_k<<<BATCH, 256>>>(mn, mx, out);
}

// round 6
// speedup vs baseline: 1.6873x; 1.6873x over previous
#include <cuda_runtime.h>
#include <cuda_fp16.h>
#include <stdint.h>

#define FDIM   1024
#define BATCH  256
#define NCLS   1000
#define CPAD   1024
#define KROW   65536
#define CB     16          // class blocks of 64
#define FS     8           // f slices of 128
#define FPC    128
#define THREADS 512
#define TSTRIDE 65         // tile row stride in 32-bit words (odd => conflict-friendly)

// ---------------- static device scratch ----------------
__device__ uint2 g_meta[FDIM * BATCH];                   // [f][b]: {t*260, half2(1-l0, l0)}
__device__ float g_part[(size_t)FS * BATCH * CPAD];      // [fs][b][c]
__device__ float g_rspart[FS * CPAD];                    // [fs][c]

// ---------------- Kernel 1: precomputed meta (transposed store) ----------------
__global__ void __launch_bounds__(1024) embed_k(const float* __restrict__ x,
                                                const float* __restrict__ mn,
                                                const float* __restrict__ mx) {
    __shared__ uint2 sm[32][33];
    const int tx = threadIdx.x & 31;
    const int ty = threadIdx.x >> 5;
    const int f0 = blockIdx.x * 32;
    const int b0 = blockIdx.y * 32;

    const float mnv = mn[0], mxv = mx[0];
    const float s = (x[(size_t)(b0 + ty) * FDIM + f0 + tx] - mnv) / (mxv - mnv) * 63.0f;

    uint2 m;
    if (s >= 0.0f && s <= 63.0f) {
        int t = (int)s;
        if (t > 62) t = 62;
        const float l0 = s - (float)t;                    // weight of vertex t+1
        const __half2 lam2 = __floats2half2_rn(1.0f - l0, l0);
        m.x = (uint32_t)t * (TSTRIDE * 4);                // byte offset of tile row t
        m.y = *(const uint32_t*)&lam2;
    } else {
        m.x = 63u * (TSTRIDE * 4);                        // zero row
        m.y = 0u;                                         // zero lambda (double safety)
    }
    sm[ty][tx] = m;
    __syncthreads();
    g_meta[(size_t)(f0 + ty) * BATCH + b0 + tx] = sm[tx][ty];
}

// ---------------- Kernel 2: f16-pair gather, [t][cls] tile ----------------
// CTA: 64 classes x 128 f x 256 b. tile[t][c] = half2(W[c][t], W[c][t+1]).
// Gather: warp w -> b in [16w,16w+16); lane -> classes {lane, lane+32}.
__global__ void __launch_bounds__(THREADS, 1) gather_k(const float* __restrict__ W) {
    __shared__ uint32_t sm_tile[2][64 * TSTRIDE];   // 2 x 16.6 KB
    __shared__ uint2    sm_meta[2][256];            // 4 KB

    const int tid  = threadIdx.x;
    const int lane = tid & 31;
    const int w    = tid >> 5;       // 0..15
    const int ly   = lane >> 4;      // row select within warp
    const int g    = lane & 15;      // column group
    const int cb   = blockIdx.x;     // 0..15
    const int fs   = blockIdx.y;     // 0..7
    const int fbase = fs * FPC;

    // fill: pass p -> class row p*32 + w*2 + ly, cols 4g..4g+3 (coalesced float4)
    int rl[2];
    const float* wp[2];
    #pragma unroll
    for (int p = 0; p < 2; p++) {
        rl[p] = p * 32 + w * 2 + ly;
        int row = cb * 64 + rl[p];
        if (row > NCLS - 1) row = NCLS - 1;
        wp[p] = W + (size_t)row * KROW + (size_t)fbase * 64 + g * 4;
    }
    const uint2* mp = g_meta + (size_t)fbase * BATCH + tid;   // valid when tid<256

    uint32_t acch[2][16];
    float    accf[2][16];
    #pragma unroll
    for (int k = 0; k < 2; k++)
        #pragma unroll
        for (int j = 0; j < 16; j++) { acch[k][j] = 0u; accf[k][j] = 0.f; }
    float rs[2] = {0.f, 0.f};

    // prologue prefetch
    float4 wv[2];
    #pragma unroll
    for (int p = 0; p < 2; p++) wv[p] = *(const float4*)(wp[p]);
    uint2 mreg = make_uint2(0u, 0u);
    if (tid < 256) mreg = mp[0];

    for (int fi = 0; fi < FPC; fi++) {
        const int buf = fi & 1;

        // ---- fill pair tile + rowsum ----
        #pragma unroll
        for (int p = 0; p < 2; p++) {
            const float4 v = wv[p];
            const float nx = __shfl_down_sync(0xffffffffu, v.x, 1);  // neighbor col-group's first
            rs[p] += (v.x + v.y) + (v.z + v.w);
            uint32_t pr[4]; __half2 h;
            h = __floats2half2_rn(v.x, v.y);  pr[0] = *(uint32_t*)&h;
            h = __floats2half2_rn(v.y, v.z);  pr[1] = *(uint32_t*)&h;
            h = __floats2half2_rn(v.z, v.w);  pr[2] = *(uint32_t*)&h;
            h = __floats2half2_rn(v.w, nx);   pr[3] = *(uint32_t*)&h;
            if (g == 15) pr[3] = 0u;          // t=63 row: zero sink
            #pragma unroll
            for (int i = 0; i < 4; i++)
                sm_tile[buf][(4 * g + i) * TSTRIDE + rl[p]] = pr[i];
        }
        if (tid < 256) sm_meta[buf][tid] = mreg;
        __syncthreads();

        // ---- prefetch next f (hidden under gather) ----
        if (fi + 1 < FPC) {
            #pragma unroll
            for (int p = 0; p < 2; p++)
                wv[p] = *(const float4*)(wp[p] + (size_t)(fi + 1) * 64);
            if (tid < 256) mreg = mp[(size_t)(fi + 1) * BATCH];
        }

        // ---- gather: 16 b's; per b: 2 conflict-free LDS.32 + 2 HFMA2 ----
        const char* tb = (const char*)sm_tile[buf];
        const uint4* mb = (const uint4*)(sm_meta[buf] + w * 16);
        #pragma unroll
        for (int q = 0; q < 8; q++) {
            const uint4 mq = mb[q];
            {
                const int j = 2 * q;
                const uint32_t* pb = (const uint32_t*)(tb + mq.x) + lane;
                const uint32_t p0 = pb[0];
                const uint32_t p1 = pb[32];
                const __half2 l2 = *(const __half2*)&mq.y;
                __half2 a0 = *(__half2*)&acch[0][j];
                __half2 a1 = *(__half2*)&acch[1][j];
                a0 = __hfma2(l2, *(const __half2*)&p0, a0);
                a1 = __hfma2(l2, *(const __half2*)&p1, a1);
                acch[0][j] = *(uint32_t*)&a0;
                acch[1][j] = *(uint32_t*)&a1;
            }
            {
                const int j = 2 * q + 1;
                const uint32_t* pb = (const uint32_t*)(tb + mq.z) + lane;
                const uint32_t p0 = pb[0];
                const uint32_t p1 = pb[32];
                const __half2 l2 = *(const __half2*)&mq.w;
                __half2 a0 = *(__half2*)&acch[0][j];
                __half2 a1 = *(__half2*)&acch[1][j];
                a0 = __hfma2(l2, *(const __half2*)&p0, a0);
                a1 = __hfma2(l2, *(const __half2*)&p1, a1);
                acch[0][j] = *(uint32_t*)&a0;
                acch[1][j] = *(uint32_t*)&a1;
            }
        }

        // ---- drain f16 accumulators to fp32 every 16 f ----
        if ((fi & 15) == 15) {
            #pragma unroll
            for (int k = 0; k < 2; k++)
                #pragma unroll
                for (int j = 0; j < 16; j++) {
                    const float2 f2 = __half22float2(*(const __half2*)&acch[k][j]);
                    accf[k][j] += f2.x + f2.y;
                    acch[k][j] = 0u;
                }
        }
    }

    // ---- rowsum: reduce over the 16 column groups (stays within half-warp) ----
    #pragma unroll
    for (int p = 0; p < 2; p++) {
        float r = rs[p];
        r += __shfl_xor_sync(0xffffffffu, r, 1);
        r += __shfl_xor_sync(0xffffffffu, r, 2);
        r += __shfl_xor_sync(0xffffffffu, r, 4);
        r += __shfl_xor_sync(0xffffffffu, r, 8);
        if (g == 0)
            g_rspart[fs * CPAD + cb * 64 + rl[p]] = r;
    }

    // ---- store partials (coalesced 128B per half) ----
    #pragma unroll
    for (int j = 0; j < 16; j++) {
        float* pp = g_part + ((size_t)fs * BATCH + w * 16 + j) * CPAD + cb * 64;
        pp[lane]      = accf[0][j];
        pp[lane + 32] = accf[1][j];
    }
}

// ---------------- Kernel 3: reduce partials + rowsum term ----------------
__global__ void __launch_bounds__(256) epi_k(const float* __restrict__ mn,
                                             const float* __restrict__ mx,
                                             float* __restrict__ out) {
    const int b = blockIdx.x;
    const float mnv = mn[0], mxv = mx[0];
    const float sc = mxv - mnv;
    for (int c = threadIdx.x; c < NCLS; c += 256) {
        float s = 0.f, rsum = 0.f;
        #pragma unroll
        for (int fsl = 0; fsl < FS; fsl++) {
            s    += g_part[((size_t)fsl * BATCH + b) * CPAD + c];
            rsum += g_rspart[fsl * CPAD + c];
        }
        out[(size_t)b * NCLS + c] = sc * s + mnv * rsum;
    }
}

// ---------------- launch ----------------
extern "C" void kernel_launch(void* const* d_in, const int* in_sizes, int n_in,
                              void* d_out, int out_size) {
    const float* x  = (const float*)d_in[0];
    const float* mn = (const float*)d_in[1];
    const float* mx = (const float*)d_in[2];
    const float* W  = (const float*)d_in[3];
    float* out = (float*)d_out;

    embed_k<<<dim3(32, 8), 1024>>>(x, mn, mx);
    gather_k<<<dim3(CB, FS), THREADS>>>(W);
    epi_k<<<BATCH, 256>>>(mn, mx, out);
}